// round 9
// baseline (speedup 1.0000x reference)
#include <cuda_runtime.h>
#include <math.h>

#define S_TOT 65536
#define CDIM 128
typedef unsigned long long ull;

// ---------------- scratch ----------------------------------------------------
__device__ float g_mean[S_TOT];
__device__ float g_rstd[S_TOT];
__device__ float g_qkv[768u * S_TOT];        // q[0:256] k[256:512] v[512:768]
__device__ float g_aout[8u * S_TOT * 32u];   // [bh][query][c]
__device__ float g_qpd[8*32*16];
__device__ float g_qph[8*32*64];
__device__ float g_qpw[8*32*64];
__device__ float g_kpd[8*32*16];
__device__ float g_kph[8*32*64];
__device__ float g_kpw[8*32*64];
__device__ int   g_idxD[8*4];
__device__ int   g_idxH[8*8];
__device__ float g_kf[8*256*32];
__device__ float g_vf[8*256*32];

// ---------------- f32x2 helpers ----------------------------------------------
__device__ __forceinline__ ull ffma2(ull a, ull b, ull c){
  ull d; asm("fma.rn.f32x2 %0, %1, %2, %3;" : "=l"(d) : "l"(a), "l"(b), "l"(c)); return d;
}
__device__ __forceinline__ ull fmul2(ull a, ull b){
  ull d; asm("mul.rn.f32x2 %0, %1, %2;" : "=l"(d) : "l"(a), "l"(b)); return d;
}
__device__ __forceinline__ ull fadd2(ull a, ull b){
  ull d; asm("add.rn.f32x2 %0, %1, %2;" : "=l"(d) : "l"(a), "l"(b)); return d;
}
__device__ __forceinline__ ull dup2(float x){
  unsigned r = __float_as_uint(x);
  ull d; asm("mov.b64 %0, {%1, %2};" : "=l"(d) : "r"(r), "r"(r)); return d;
}
__device__ __forceinline__ ull pack2(float x, float y){
  ull d; asm("mov.b64 %0, {%1, %2};" : "=l"(d) : "r"(__float_as_uint(x)), "r"(__float_as_uint(y))); return d;
}
__device__ __forceinline__ float2 unpack2(ull v){
  unsigned lo, hi; asm("mov.b64 {%0, %1}, %2;" : "=r"(lo), "=r"(hi) : "l"(v));
  return make_float2(__uint_as_float(lo), __uint_as_float(hi));
}
__device__ __forceinline__ float ex2f(float x){
  float r; asm("ex2.approx.f32 %0, %1;" : "=f"(r) : "f"(x)); return r;
}

__device__ __forceinline__ float warp_sum(float v){
  #pragma unroll
  for (int o=16;o;o>>=1) v += __shfl_xor_sync(0xffffffffu, v, o);
  return v;
}

// ---------------- 1) LayerNorm stats -----------------------------------------
__global__ void k_ln_stats(const float* __restrict__ x){
  int s = blockIdx.x*blockDim.x + threadIdx.x;
  float sum=0.f, sq=0.f;
  #pragma unroll 8
  for (int c=0;c<CDIM;c++){
    float v = x[(size_t)c*S_TOT + s];
    sum += v; sq += v*v;
  }
  float m = sum*(1.f/128.f);
  float var = sq*(1.f/128.f) - m*m;
  g_mean[s] = m;
  g_rstd[s] = 1.f/sqrtf(var + 1e-5f);
}

// ---------------- 2/12) SGEMM: 128x256 tile, 256 thr, 8x16/thread, f32x2 -----
// (exact R2 configuration — proven 888.6us baseline)
template<int KDIM, int MODE>
__global__ void __launch_bounds__(256) k_gemm(
    const float* __restrict__ A, const float* __restrict__ Bx,
    float* __restrict__ Cx, const float* __restrict__ gg,
    const float* __restrict__ bb, const float* __restrict__ bias)
{
  const float* B = (MODE==0) ? Bx : g_aout;
  float* C = (MODE==0) ? g_qkv : Cx;
  __shared__ __align__(16) float As[2][8][128];
  __shared__ __align__(16) float Bs[2][8][256];
  __shared__ __align__(16) float NormS[16][256];
  int t = threadIdx.x;
  int m0 = blockIdx.y*128, n0 = blockIdx.x*256;
  int tx = t & 15, ty = t >> 4;

  int lar = t >> 1, lak = (t & 1) * 4;     // A loader: row, k-quad
  int lbk = t >> 5, lbc = (t & 31) * 4;    // B loader: k-row, col base

  float4 mean4[2], rstd4[2];
  if (MODE==0){
    #pragma unroll
    for (int h=0;h<2;h++){
      mean4[h] = *(const float4*)&g_mean[n0 + lbc + h*128];
      rstd4[h] = *(const float4*)&g_rstd[n0 + lbc + h*128];
    }
  }

  ull acc[8][8];
  #pragma unroll
  for (int i=0;i<8;i++)
    #pragma unroll
    for (int j=0;j<8;j++) acc[i][j] = 0ull;

  const int NS = KDIM/8;
  {
    float4 a4 = *(const float4*)(A + (size_t)(m0+lar)*KDIM + lak);
    As[0][lak+0][lar]=a4.x; As[0][lak+1][lar]=a4.y;
    As[0][lak+2][lar]=a4.z; As[0][lak+3][lar]=a4.w;
    float gk=1.f, bk=0.f;
    if (MODE==0){ gk = gg[lbk]; bk = bb[lbk]; }
    #pragma unroll
    for (int h=0;h<2;h++){
      float4 b4 = *(const float4*)(B + (size_t)lbk*S_TOT + n0 + lbc + h*128);
      if (MODE==0){
        b4.x = (b4.x-mean4[h].x)*rstd4[h].x*gk + bk;
        b4.y = (b4.y-mean4[h].y)*rstd4[h].y*gk + bk;
        b4.z = (b4.z-mean4[h].z)*rstd4[h].z*gk + bk;
        b4.w = (b4.w-mean4[h].w)*rstd4[h].w*gk + bk;
      }
      *(float4*)&Bs[0][lbk][lbc + h*128] = b4;
    }
  }
  __syncthreads();
  int st = 0;
  for (int ks=0; ks<NS; ks++){
    float4 a4n; float4 b4n[2];
    bool more = (ks+1 < NS);
    if (more){
      int k0 = (ks+1)*8;
      a4n = *(const float4*)(A + (size_t)(m0+lar)*KDIM + k0 + lak);
      float gk=1.f, bk=0.f;
      if (MODE==0){ gk = gg[k0+lbk]; bk = bb[k0+lbk]; }
      #pragma unroll
      for (int h=0;h<2;h++){
        float4 b4 = *(const float4*)(B + (size_t)(k0+lbk)*S_TOT + n0 + lbc + h*128);
        if (MODE==0){
          b4.x = (b4.x-mean4[h].x)*rstd4[h].x*gk + bk;
          b4.y = (b4.y-mean4[h].y)*rstd4[h].y*gk + bk;
          b4.z = (b4.z-mean4[h].z)*rstd4[h].z*gk + bk;
          b4.w = (b4.w-mean4[h].w)*rstd4[h].w*gk + bk;
        }
        b4n[h] = b4;
      }
    }
    #pragma unroll
    for (int kk=0;kk<8;kk++){
      float4 av0 = *(const float4*)&As[st][kk][ty*8];
      float4 av1 = *(const float4*)&As[st][kk][ty*8+4];
      float a[8] = {av0.x,av0.y,av0.z,av0.w,av1.x,av1.y,av1.z,av1.w};
      ull b2[8];
      #pragma unroll
      for (int c=0;c<4;c++){
        ulonglong2 bp = *(const ulonglong2*)&Bs[st][kk][tx*4 + c*64];
        b2[c*2] = bp.x; b2[c*2+1] = bp.y;
      }
      #pragma unroll
      for (int i=0;i<8;i++){
        ull da = dup2(a[i]);
        #pragma unroll
        for (int j=0;j<8;j++) acc[i][j] = ffma2(da, b2[j], acc[i][j]);
      }
    }
    if (more){
      int ns = st^1;
      As[ns][lak+0][lar]=a4n.x; As[ns][lak+1][lar]=a4n.y;
      As[ns][lak+2][lar]=a4n.z; As[ns][lak+3][lar]=a4n.w;
      *(float4*)&Bs[ns][lbk][lbc]       = b4n[0];
      *(float4*)&Bs[ns][lbk][lbc + 128] = b4n[1];
      __syncthreads();
      st = ns;
    }
  }

  if (MODE==0 && m0 < 512){
    ull ss2[8];
    #pragma unroll
    for (int j=0;j<8;j++){
      ull s2 = 0ull;
      #pragma unroll
      for (int i=0;i<8;i++) s2 = ffma2(acc[i][j], acc[i][j], s2);
      ss2[j] = s2;
    }
    __syncthreads();
    #pragma unroll
    for (int j=0;j<8;j++){
      int col = tx*4 + (j>>1)*64 + (j&1)*2;
      *(ull*)&NormS[ty][col] = ss2[j];
    }
    __syncthreads();
    int g4 = (ty>>2)*4;
    #pragma unroll
    for (int j=0;j<8;j++){
      int col = tx*4 + (j>>1)*64 + (j&1)*2;
      ull n2 = *(const ull*)&NormS[g4+0][col];
      n2 = fadd2(n2, *(const ull*)&NormS[g4+1][col]);
      n2 = fadd2(n2, *(const ull*)&NormS[g4+2][col]);
      n2 = fadd2(n2, *(const ull*)&NormS[g4+3][col]);
      float2 nf = unpack2(n2);
      float f0 = 1.f/fmaxf(sqrtf(nf.x), 1e-12f);
      float f1 = 1.f/fmaxf(sqrtf(nf.y), 1e-12f);
      ull fv = pack2(f0, f1);
      #pragma unroll
      for (int i=0;i<8;i++) acc[i][j] = fmul2(acc[i][j], fv);
    }
  }

  #pragma unroll
  for (int i=0;i<8;i++){
    int m = m0 + ty*8 + i;
    float bo = (MODE==1) ? bias[m] : 0.f;
    #pragma unroll
    for (int c=0;c<4;c++){
      float2 p0 = unpack2(acc[i][c*2]);
      float2 p1 = unpack2(acc[i][c*2+1]);
      float4 o = make_float4(p0.x+bo, p0.y+bo, p1.x+bo, p1.y+bo);
      *(float4*)(C + (size_t)m*S_TOT + n0 + tx*4 + c*64) = o;
    }
  }
}

// ---------------- 4) probes --------------------------------------------------
__global__ void k_probes(){
  int bh = blockIdx.x >> 5, c = blockIdx.x & 31;
  int t = threadIdx.x, lane = t & 31;
  const float* qp = g_qkv + (size_t)(bh*32+c)*S_TOT;
  const float* kp = g_qkv + (size_t)(256+bh*32+c)*S_TOT;
  __shared__ float sqd[16], skd[16], sqh[64], sqw[64];
  if (t<64){ sqh[t]=0.f; sqw[t]=0.f; }
  if (t<16){ sqd[t]=0.f; skd[t]=0.f; }
  __syncthreads();
  float qW = 0.f;
  float qH[8];
  #pragma unroll
  for (int i=0;i<8;i++) qH[i]=0.f;
  #pragma unroll 1
  for (int m=0;m<16;m++){
    float qD=0.f, kD=0.f;
    #pragma unroll
    for (int i2=0;i2<8;i2++){
      int s = m*4096 + i2*512 + t;
      float qv = fabsf(qp[s]);
      float kv = fabsf(kp[s]);
      qD += qv; kD += kv; qW += qv; qH[i2] += qv;
    }
    qD = warp_sum(qD); kD = warp_sum(kD);
    if (lane==0){ atomicAdd(&sqd[m], qD); atomicAdd(&skd[m], kD); }
  }
  int hb = t >> 6;
  #pragma unroll
  for (int i2=0;i2<8;i2++){
    float v = warp_sum(qH[i2]);
    if (lane==0) atomicAdd(&sqh[i2*8 + hb], v);
  }
  atomicAdd(&sqw[t & 63], qW);
  __syncthreads();
  if (t<16){ g_qpd[(bh*32+c)*16 + t] = sqd[t]; g_kpd[(bh*32+c)*16 + t] = skd[t]; }
  if (t<64){ g_qph[(bh*32+c)*64 + t] = sqh[t]; g_qpw[(bh*32+c)*64 + t] = sqw[t]; }
}

// ---------------- 6) k probe over h (+ fused top-kD, publishes g_idxD) ------
__global__ void k_kprobe_h(){
  int bh = blockIdx.x>>5, c = blockIdx.x&31;
  int t = threadIdx.x, lane = t&31;
  const float* kp = g_qkv + (size_t)(256+bh*32+c)*S_TOT;
  __shared__ float sh[64];
  __shared__ float scD[16];
  __shared__ int sd[4];
  if (t<64) sh[t]=0.f;
  if (t < 32){
    float qv[16], kv[16];
    const float* qb = g_qpd + (bh*32+t)*16;
    const float* kb = g_kpd + (bh*32+t)*16;
    #pragma unroll
    for (int d=0;d<16;d++){ qv[d]=qb[d]; kv[d]=kb[d]; }
    #pragma unroll
    for (int d=0;d<16;d++){
      float v = warp_sum(qv[d]*kv[d]);
      if (t==0) scD[d]=v;
    }
    if (t==0){
      unsigned used=0;
      for (int r=0;r<4;r++){
        float best=-3.4e38f; int bi=0;
        for (int d=0;d<16;d++) if(!((used>>d)&1u) && scD[d]>best){best=scD[d];bi=d;}
        used|=1u<<bi; sd[r]=bi;
      }
    }
  }
  __syncthreads();
  if (c==0 && t<4) g_idxD[bh*4+t]=sd[t];
  float acc[8];
  #pragma unroll
  for (int i=0;i<8;i++) acc[i]=0.f;
  #pragma unroll 1
  for (int di=0; di<4; di++){
    int d = sd[di];
    #pragma unroll
    for (int i2=0;i2<8;i2++){
      int s = d*4096 + i2*512 + t;
      acc[i2] += fabsf(kp[s]);
    }
  }
  int hb = t>>6;
  #pragma unroll
  for (int i2=0;i2<8;i2++){
    float v = warp_sum(acc[i2]);
    if (lane==0) atomicAdd(&sh[i2*8+hb], v);
  }
  __syncthreads();
  if (t<64) g_kph[(bh*32+c)*64+t] = sh[t];
}

// ---------------- 8) k probe over w (+ fused top-kH, publishes g_idxH) ------
__global__ void k_kprobe_w(){
  int bh = blockIdx.x>>5, c = blockIdx.x&31;
  int t = threadIdx.x;
  const float* kp = g_qkv + (size_t)(256+bh*32+c)*S_TOT;
  __shared__ float sw[64];
  __shared__ float scH[64];
  __shared__ int sd[4], shh[8];
  if (t<64) sw[t]=0.f;
  if (t<4)  sd[t]=g_idxD[bh*4+t];
  {
    int w = t>>5, lane = t&31;
    const float* qb = g_qph + (bh*32+lane)*64;
    const float* kb = g_kph + (bh*32+lane)*64;
    #pragma unroll
    for (int i=0;i<8;i++){
      int d = w*8+i;
      float v = warp_sum(qb[d]*kb[d]);
      if (lane==0) scH[d]=v;
    }
  }
  __syncthreads();
  if (t==0){
    unsigned long long used=0ull;
    for (int r=0;r<8;r++){
      float best=-3.4e38f; int bi=0;
      for (int d=0;d<64;d++) if(!((used>>d)&1ull) && scH[d]>best){best=scH[d];bi=d;}
      used|=1ull<<bi; shh[r]=bi;
    }
  }
  __syncthreads();
  if (c==0 && t<8) g_idxH[bh*8+t]=shh[t];
  float acc = 0.f;
  int r = t>>6, w = t&63;
  #pragma unroll
  for (int it=0; it<8; it++){
    int combo = r + it*4;
    int di = combo>>3, hi = combo&7;
    int s = sd[di]*4096 + shh[hi]*64 + w;
    acc += fabsf(kp[s]);
  }
  atomicAdd(&sw[w], acc);
  __syncthreads();
  if (t<64) g_kpw[(bh*32+c)*64+t] = sw[t];
}

// ---------------- 10) gather pruned K/V (+ fused top-kW, local) --------------
__global__ void k_gather(){
  int bh = blockIdx.y;
  int t = threadIdx.x;
  __shared__ float scW[64];
  __shared__ int sd[4], sh8[8], sw8[8];
  if (t<4) sd[t]=g_idxD[bh*4+t];
  if (t<8) sh8[t]=g_idxH[bh*8+t];
  {
    int w = t>>5, lane = t&31;
    const float* qb = g_qpw + (bh*32+lane)*64;
    const float* kb = g_kpw + (bh*32+lane)*64;
    #pragma unroll
    for (int i=0;i<8;i++){
      int d = w*8+i;
      float v = warp_sum(qb[d]*kb[d]);
      if (lane==0) scW[d]=v;
    }
  }
  __syncthreads();
  if (t==0){
    unsigned long long used=0ull;
    for (int r=0;r<8;r++){
      float best=-3.4e38f; int bi=0;
      for (int d=0;d<64;d++) if(!((used>>d)&1ull) && scW[d]>best){best=scW[d];bi=d;}
      used|=1ull<<bi; sw8[r]=bi;
    }
  }
  __syncthreads();
  int j = blockIdx.x*8 + (t>>5);
  int c = t & 31;
  int di = j>>6, hi = (j>>3)&7, wi = j&7;
  int s = sd[di]*4096 + sh8[hi]*64 + sw8[wi];
  g_kf[(bh*256+j)*32 + c] = g_qkv[(size_t)(256+bh*32+c)*S_TOT + s];
  g_vf[(bh*256+j)*32 + c] = g_qkv[(size_t)(512+bh*32+c)*S_TOT + s];
}

// ---------------- 11) attention: 256 thr, 2 queries/thread, FORCED 2 CTAs/SM -
__global__ void __launch_bounds__(256, 2) k_attn(){
  extern __shared__ float smem[];
  float* sk = smem;            // 256*32
  float* sv = smem + 8192;     // 256*32
  int bh = blockIdx.y, t = threadIdx.x;
  const float4* kf4 = (const float4*)(g_kf + (size_t)bh*8192);
  const float4* vf4 = (const float4*)(g_vf + (size_t)bh*8192);
  #pragma unroll
  for (int i=0;i<8;i++){
    ((float4*)sk)[t + i*256] = kf4[t + i*256];
    ((float4*)sv)[t + i*256] = vf4[t + i*256];
  }
  __syncthreads();
  const float LOG2E = 1.4426950408889634f;
  int s0 = blockIdx.x*512 + t;
  int s1 = s0 + 256;
  ull q0[16], q1[16];
  #pragma unroll
  for (int c=0;c<16;c++){
    const float* p = g_qkv + (size_t)(bh*32 + 2*c)*S_TOT;
    q0[c] = pack2(p[s0]*LOG2E, p[S_TOT + s0]*LOG2E);
    q1[c] = pack2(p[s1]*LOG2E, p[S_TOT + s1]*LOG2E);
  }
  ull o0[16], o1[16];
  #pragma unroll
  for (int c=0;c<16;c++){ o0[c]=0ull; o1[c]=0ull; }
  float l0=0.f, l1=0.f;
  #pragma unroll 2
  for (int j=0;j<256;j++){
    const ulonglong2* kp = (const ulonglong2*)(sk + j*32);
    ull sA0=0ull,sA1=0ull,sB0=0ull,sB1=0ull;
    #pragma unroll
    for (int u=0;u<8;u++){
      ulonglong2 x = kp[u];
      sA0 = ffma2(q0[2*u],   x.x, sA0);
      sA1 = ffma2(q0[2*u+1], x.y, sA1);
      sB0 = ffma2(q1[2*u],   x.x, sB0);
      sB1 = ffma2(q1[2*u+1], x.y, sB1);
    }
    float2 fa = unpack2(fadd2(sA0,sA1));
    float2 fb = unpack2(fadd2(sB0,sB1));
    float p0 = ex2f(fa.x + fa.y);
    float p1 = ex2f(fb.x + fb.y);
    l0 += p0; l1 += p1;
    ull pd0 = dup2(p0), pd1 = dup2(p1);
    const ulonglong2* vp = (const ulonglong2*)(sv + j*32);
    #pragma unroll
    for (int u=0;u<8;u++){
      ulonglong2 x = vp[u];
      o0[2*u]   = ffma2(pd0, x.x, o0[2*u]);
      o0[2*u+1] = ffma2(pd0, x.y, o0[2*u+1]);
      o1[2*u]   = ffma2(pd1, x.x, o1[2*u]);
      o1[2*u+1] = ffma2(pd1, x.y, o1[2*u+1]);
    }
  }
  ull d0 = dup2(1.f/l0), d1 = dup2(1.f/l1);
  float4* ob0 = (float4*)(g_aout + ((size_t)bh*S_TOT + (size_t)s0)*32u);
  #pragma unroll
  for (int u=0;u<8;u++){
    float2 a = unpack2(fmul2(o0[2*u], d0));
    float2 b = unpack2(fmul2(o0[2*u+1], d0));
    ob0[u] = make_float4(a.x, a.y, b.x, b.y);
  }
  float4* ob1 = (float4*)(g_aout + ((size_t)bh*S_TOT + (size_t)s1)*32u);
  #pragma unroll
  for (int u=0;u<8;u++){
    float2 a = unpack2(fmul2(o1[2*u], d1));
    float2 b = unpack2(fmul2(o1[2*u+1], d1));
    ob1[u] = make_float4(a.x, a.y, b.x, b.y);
  }
}

// ---------------- host ------------------------------------------------------
extern "C" void kernel_launch(void* const* d_in, const int* in_sizes, int n_in,
                              void* d_out, int out_size) {
  (void)in_sizes; (void)n_in; (void)out_size;
  const float* x     = (const float*)d_in[0];
  const float* g     = (const float*)d_in[1];
  const float* b     = (const float*)d_in[2];
  const float* wqkv  = (const float*)d_in[3];
  const float* wout  = (const float*)d_in[4];
  const float* bout  = (const float*)d_in[5];
  float* out = (float*)d_out;

  k_ln_stats<<<S_TOT/256, 256>>>(x);
  k_gemm<128,0><<<dim3(S_TOT/256, 6), 256>>>(wqkv, x, nullptr, g, b, nullptr);
  k_probes<<<256, 512>>>();
  k_kprobe_h<<<256, 512>>>();
  k_kprobe_w<<<256, 256>>>();
  k_gather<<<dim3(32, 8), 256>>>();
  cudaFuncSetAttribute((const void*)k_attn,
                       cudaFuncAttributeMaxDynamicSharedMemorySize, 65536);
  k_attn<<<dim3(S_TOT/512, 8), 256, 65536>>>();
  k_gemm<256,1><<<dim3(S_TOT/256, 1), 256>>>(wout, nullptr, out, nullptr, nullptr, bout);
}

// round 13
// speedup vs baseline: 1.4293x; 1.4293x over previous
#include <cuda_runtime.h>
#include <cuda_bf16.h>
#include <math.h>

#define S_TOT 65536
#define CDIM 128
typedef unsigned long long ull;

// ---------------- scratch ----------------------------------------------------
__device__ float g_mean[S_TOT];   // unused at runtime (template compile)
__device__ float g_rstd[S_TOT];
__device__ float g_qkv[768u * S_TOT];        // q[0:256] k[256:512] v[512:768]
__device__ float g_aout[8u * S_TOT * 32u];   // [bh][query][c]
__device__ float g_qpd[8*32*16];
__device__ float g_qph[8*32*64];
__device__ float g_qpw[8*32*64];
__device__ float g_kpd[8*32*16];
__device__ float g_kph[8*32*64];
__device__ float g_kpw[8*32*64];
__device__ int   g_idxD[8*4];
__device__ int   g_idxH[8*8];
__device__ float g_kf[8*256*32];
__device__ float g_vf[8*256*32];
// split-bf16 concatenated operands: K' = 384
// A' = [Whi | Whi | Wlo]  (768 x 384),  B' = [Xhi | Xlo | Xhi]  (65536 x 384)
__device__ __align__(16) __nv_bfloat16 g_w[768u*384u];
__device__ __align__(16) __nv_bfloat16 g_xn[(size_t)S_TOT*384u];

// ---------------- f32x2 helpers ----------------------------------------------
__device__ __forceinline__ ull ffma2(ull a, ull b, ull c){
  ull d; asm("fma.rn.f32x2 %0, %1, %2, %3;" : "=l"(d) : "l"(a), "l"(b), "l"(c)); return d;
}
__device__ __forceinline__ ull fmul2(ull a, ull b){
  ull d; asm("mul.rn.f32x2 %0, %1, %2;" : "=l"(d) : "l"(a), "l"(b)); return d;
}
__device__ __forceinline__ ull fadd2(ull a, ull b){
  ull d; asm("add.rn.f32x2 %0, %1, %2;" : "=l"(d) : "l"(a), "l"(b)); return d;
}
__device__ __forceinline__ ull dup2(float x){
  unsigned r = __float_as_uint(x);
  ull d; asm("mov.b64 %0, {%1, %2};" : "=l"(d) : "r"(r), "r"(r)); return d;
}
__device__ __forceinline__ ull pack2(float x, float y){
  ull d; asm("mov.b64 %0, {%1, %2};" : "=l"(d) : "r"(__float_as_uint(x)), "r"(__float_as_uint(y))); return d;
}
__device__ __forceinline__ float2 unpack2(ull v){
  unsigned lo, hi; asm("mov.b64 {%0, %1}, %2;" : "=r"(lo), "=r"(hi) : "l"(v));
  return make_float2(__uint_as_float(lo), __uint_as_float(hi));
}
__device__ __forceinline__ float ex2f(float x){
  float r; asm("ex2.approx.f32 %0, %1;" : "=f"(r) : "f"(x)); return r;
}
__device__ __forceinline__ float warp_sum(float v){
  #pragma unroll
  for (int o=16;o;o>>=1) v += __shfl_xor_sync(0xffffffffu, v, o);
  return v;
}

// ---------------- 0a) build A' = [Whi | Whi | Wlo] ---------------------------
__global__ void k_wsplit(const float* __restrict__ w){
  int i = blockIdx.x*256 + threadIdx.x;   // 98304 total
  int m = i >> 7, c = i & 127;
  float v = w[i];
  __nv_bfloat16 h = __float2bfloat16(v);
  __nv_bfloat16 l = __float2bfloat16(v - __bfloat162float(h));
  g_w[(size_t)m*384 + c]       = h;
  g_w[(size_t)m*384 + 128 + c] = h;
  g_w[(size_t)m*384 + 256 + c] = l;
}

// ---------------- 0b) LayerNorm + split + transpose: B' = [Xhi|Xlo|Xhi] ------
__global__ void __launch_bounds__(128) k_lnsplit(const float* __restrict__ x,
    const float* __restrict__ gg, const float* __restrict__ bb){
  __shared__ ull sh[128][33];
  int t = threadIdx.x;
  int sBase = blockIdx.x*128;
  int s = sBase + t;
  float xv[128];
  float sum=0.f, sq=0.f;
  #pragma unroll 4
  for (int c=0;c<128;c++){
    float v = x[(size_t)c*S_TOT + s];
    xv[c]=v; sum+=v; sq+=v*v;
  }
  float mn = sum*(1.f/128.f);
  float rs = 1.f/sqrtf(sq*(1.f/128.f)-mn*mn + 1e-5f);
  #pragma unroll 4
  for (int c=0;c<128;c++) xv[c] = (xv[c]-mn)*rs*gg[c] + bb[c];
  // ---- HI pass: write to cols [0,128) and duplicate at [256,384) ----
  #pragma unroll
  for (int q=0;q<32;q++){
    ull p = 0;
    #pragma unroll
    for (int e=0;e<4;e++){
      __nv_bfloat16 h = __float2bfloat16(xv[q*4+e]);
      unsigned short u = *(unsigned short*)&h;
      p |= (ull)u << (e*16);
    }
    sh[t][q] = p;
  }
  __syncthreads();
  #pragma unroll
  for (int it=0; it<16; it++){
    int chunk = it*128 + t;
    int row = chunk>>4, seg = chunk&15;
    ulonglong2 v = make_ulonglong2(sh[row][seg*2], sh[row][seg*2+1]);
    __nv_bfloat16* base = g_xn + ((size_t)(sBase+row))*384 + seg*8;
    *(ulonglong2*)base = v;
    *(ulonglong2*)(base + 256) = v;
  }
  __syncthreads();
  // ---- LO pass: write to cols [128,256) ----
  #pragma unroll
  for (int q=0;q<32;q++){
    ull p = 0;
    #pragma unroll
    for (int e=0;e<4;e++){
      float v = xv[q*4+e];
      __nv_bfloat16 h = __float2bfloat16(v);
      __nv_bfloat16 l = __float2bfloat16(v - __bfloat162float(h));
      unsigned short u = *(unsigned short*)&l;
      p |= (ull)u << (e*16);
    }
    sh[t][q] = p;
  }
  __syncthreads();
  #pragma unroll
  for (int it=0; it<16; it++){
    int chunk = it*128 + t;
    int row = chunk>>4, seg = chunk&15;
    ulonglong2 v = make_ulonglong2(sh[row][seg*2], sh[row][seg*2+1]);
    *(ulonglong2*)(g_xn + ((size_t)(sBase+row))*384 + 128 + seg*8) = v;
  }
}

// ---------------- 2) QKV GEMM via mma.sync bf16, K'=384 ----------------------
// CTA: 128 thr (4 warps 2x2), tile 128m x 64n. Warp: 64m x 32n = 4x4 frags.
// Fused per-head l2-norm in epilogue for q,k rows (m < 512).
__device__ __forceinline__ void mma16816(float* c, const unsigned* a, const unsigned* b){
  asm volatile(
    "mma.sync.aligned.m16n8k16.row.col.f32.bf16.bf16.f32 "
    "{%0,%1,%2,%3}, {%4,%5,%6,%7}, {%8,%9}, {%0,%1,%2,%3};"
    : "+f"(c[0]), "+f"(c[1]), "+f"(c[2]), "+f"(c[3])
    : "r"(a[0]), "r"(a[1]), "r"(a[2]), "r"(a[3]), "r"(b[0]), "r"(b[1]));
}

#define APITCH 40
__global__ void __launch_bounds__(128) k_qkv_mma(){
  __shared__ __align__(16) __nv_bfloat16 As[128*APITCH];  // 10240 B
  __shared__ __align__(16) __nv_bfloat16 Bs[64*APITCH];   //  5120 B
  int t = threadIdx.x;
  int wid = t>>5, lane = t&31;
  int g = lane>>2, tig = lane&3;
  int wm = wid>>1, wn = wid&1;
  int m0 = blockIdx.y*128, n0 = blockIdx.x*64;

  float c[4][4][4];
  #pragma unroll
  for (int mt=0;mt<4;mt++)
    #pragma unroll
    for (int nt=0;nt<4;nt++)
      #pragma unroll
      for (int e=0;e<4;e++) c[mt][nt][e]=0.f;

  for (int k0=0;k0<384;k0+=32){
    __syncthreads();
    {
      // FIX (R12 bug): load the FULL 32-wide k-chunk per A row (4 x 16B).
      const ulonglong2* src = (const ulonglong2*)(g_w + (size_t)(m0+t)*384 + k0);
      ulonglong2 v0 = src[0], v1 = src[1], v2 = src[2], v3 = src[3];
      *(ulonglong2*)&As[t*APITCH]       = v0;
      *(ulonglong2*)&As[t*APITCH + 8]   = v1;
      *(ulonglong2*)&As[t*APITCH + 16]  = v2;
      *(ulonglong2*)&As[t*APITCH + 24]  = v3;
    }
    {
      int r = t>>1, h = (t&1)*16;
      ulonglong2 v = *(const ulonglong2*)(g_xn + (size_t)(n0+r)*384 + k0 + h);
      *(ulonglong2*)&Bs[r*APITCH + h]     = v;
      ulonglong2 v2 = *(const ulonglong2*)(g_xn + (size_t)(n0+r)*384 + k0 + h + 8);
      *(ulonglong2*)&Bs[r*APITCH + h + 8] = v2;
    }
    __syncthreads();
    #pragma unroll
    for (int ks=0;ks<2;ks++){
      int kk = ks*16;
      unsigned a[4][4], b[4][2];
      #pragma unroll
      for (int mt=0;mt<4;mt++){
        int mr = (wm*64 + mt*16 + g)*APITCH + kk + tig*2;
        a[mt][0] = *(const unsigned*)&As[mr];
        a[mt][1] = *(const unsigned*)&As[mr + 8*APITCH];
        a[mt][2] = *(const unsigned*)&As[mr + 8];
        a[mt][3] = *(const unsigned*)&As[mr + 8*APITCH + 8];
      }
      #pragma unroll
      for (int nt=0;nt<4;nt++){
        int nr = (wn*32 + nt*8 + g)*APITCH + kk + tig*2;
        b[nt][0] = *(const unsigned*)&Bs[nr];
        b[nt][1] = *(const unsigned*)&Bs[nr + 8];
      }
      #pragma unroll
      for (int mt=0;mt<4;mt++)
        #pragma unroll
        for (int nt=0;nt<4;nt++)
          mma16816(c[mt][nt], a[mt], b[nt]);
    }
  }

  // ---- fused l2-norm for q,k rows: head = 32 rows = 2 m-tiles ----
  if (m0 < 512){
    #pragma unroll
    for (int hh=0; hh<2; hh++){
      #pragma unroll
      for (int nt=0; nt<4; nt++){
        float* f0 = c[hh*2][nt];
        float* f1 = c[hh*2+1][nt];
        float sA = f0[0]*f0[0] + f0[2]*f0[2] + f1[0]*f1[0] + f1[2]*f1[2];
        float sB = f0[1]*f0[1] + f0[3]*f0[3] + f1[1]*f1[1] + f1[3]*f1[3];
        #pragma unroll
        for (int o=4;o<=16;o<<=1){
          sA += __shfl_xor_sync(0xffffffffu, sA, o);
          sB += __shfl_xor_sync(0xffffffffu, sB, o);
        }
        float fA = 1.f/fmaxf(sqrtf(sA), 1e-12f);
        float fB = 1.f/fmaxf(sqrtf(sB), 1e-12f);
        f0[0]*=fA; f0[2]*=fA; f1[0]*=fA; f1[2]*=fA;
        f0[1]*=fB; f0[3]*=fB; f1[1]*=fB; f1[3]*=fB;
      }
    }
  }

  #pragma unroll
  for (int mt=0;mt<4;mt++){
    int m = m0 + wm*64 + mt*16;
    #pragma unroll
    for (int nt=0;nt<4;nt++){
      int s = n0 + wn*32 + nt*8 + tig*2;
      *(float2*)(g_qkv + (size_t)(m+g)*S_TOT + s)   = make_float2(c[mt][nt][0], c[mt][nt][1]);
      *(float2*)(g_qkv + (size_t)(m+g+8)*S_TOT + s) = make_float2(c[mt][nt][2], c[mt][nt][3]);
    }
  }
}

// ---------------- 12) SGEMM (proj only; R2-proven config) --------------------
template<int KDIM, int MODE>
__global__ void __launch_bounds__(256) k_gemm(
    const float* __restrict__ A, const float* __restrict__ Bx,
    float* __restrict__ Cx, const float* __restrict__ gg,
    const float* __restrict__ bb, const float* __restrict__ bias)
{
  const float* B = (MODE==0) ? Bx : g_aout;
  float* C = (MODE==0) ? g_qkv : Cx;
  __shared__ __align__(16) float As[2][8][128];
  __shared__ __align__(16) float Bs[2][8][256];
  __shared__ __align__(16) float NormS[16][256];
  int t = threadIdx.x;
  int m0 = blockIdx.y*128, n0 = blockIdx.x*256;
  int tx = t & 15, ty = t >> 4;

  int lar = t >> 1, lak = (t & 1) * 4;
  int lbk = t >> 5, lbc = (t & 31) * 4;

  float4 mean4[2], rstd4[2];
  if (MODE==0){
    #pragma unroll
    for (int h=0;h<2;h++){
      mean4[h] = *(const float4*)&g_mean[n0 + lbc + h*128];
      rstd4[h] = *(const float4*)&g_rstd[n0 + lbc + h*128];
    }
  }

  ull acc[8][8];
  #pragma unroll
  for (int i=0;i<8;i++)
    #pragma unroll
    for (int j=0;j<8;j++) acc[i][j] = 0ull;

  const int NS = KDIM/8;
  {
    float4 a4 = *(const float4*)(A + (size_t)(m0+lar)*KDIM + lak);
    As[0][lak+0][lar]=a4.x; As[0][lak+1][lar]=a4.y;
    As[0][lak+2][lar]=a4.z; As[0][lak+3][lar]=a4.w;
    float gk=1.f, bk=0.f;
    if (MODE==0){ gk = gg[lbk]; bk = bb[lbk]; }
    #pragma unroll
    for (int h=0;h<2;h++){
      float4 b4 = *(const float4*)(B + (size_t)lbk*S_TOT + n0 + lbc + h*128);
      if (MODE==0){
        b4.x = (b4.x-mean4[h].x)*rstd4[h].x*gk + bk;
        b4.y = (b4.y-mean4[h].y)*rstd4[h].y*gk + bk;
        b4.z = (b4.z-mean4[h].z)*rstd4[h].z*gk + bk;
        b4.w = (b4.w-mean4[h].w)*rstd4[h].w*gk + bk;
      }
      *(float4*)&Bs[0][lbk][lbc + h*128] = b4;
    }
  }
  __syncthreads();
  int st = 0;
  for (int ks=0; ks<NS; ks++){
    float4 a4n; float4 b4n[2];
    bool more = (ks+1 < NS);
    if (more){
      int k0 = (ks+1)*8;
      a4n = *(const float4*)(A + (size_t)(m0+lar)*KDIM + k0 + lak);
      float gk=1.f, bk=0.f;
      if (MODE==0){ gk = gg[k0+lbk]; bk = bb[k0+lbk]; }
      #pragma unroll
      for (int h=0;h<2;h++){
        float4 b4 = *(const float4*)(B + (size_t)(k0+lbk)*S_TOT + n0 + lbc + h*128);
        if (MODE==0){
          b4.x = (b4.x-mean4[h].x)*rstd4[h].x*gk + bk;
          b4.y = (b4.y-mean4[h].y)*rstd4[h].y*gk + bk;
          b4.z = (b4.z-mean4[h].z)*rstd4[h].z*gk + bk;
          b4.w = (b4.w-mean4[h].w)*rstd4[h].w*gk + bk;
        }
        b4n[h] = b4;
      }
    }
    #pragma unroll
    for (int kk=0;kk<8;kk++){
      float4 av0 = *(const float4*)&As[st][kk][ty*8];
      float4 av1 = *(const float4*)&As[st][kk][ty*8+4];
      float a[8] = {av0.x,av0.y,av0.z,av0.w,av1.x,av1.y,av1.z,av1.w};
      ull b2[8];
      #pragma unroll
      for (int cc=0;cc<4;cc++){
        ulonglong2 bp = *(const ulonglong2*)&Bs[st][kk][tx*4 + cc*64];
        b2[cc*2] = bp.x; b2[cc*2+1] = bp.y;
      }
      #pragma unroll
      for (int i=0;i<8;i++){
        ull da = dup2(a[i]);
        #pragma unroll
        for (int j=0;j<8;j++) acc[i][j] = ffma2(da, b2[j], acc[i][j]);
      }
    }
    if (more){
      int ns = st^1;
      As[ns][lak+0][lar]=a4n.x; As[ns][lak+1][lar]=a4n.y;
      As[ns][lak+2][lar]=a4n.z; As[ns][lak+3][lar]=a4n.w;
      *(float4*)&Bs[ns][lbk][lbc]       = b4n[0];
      *(float4*)&Bs[ns][lbk][lbc + 128] = b4n[1];
      __syncthreads();
      st = ns;
    }
  }

  if (MODE==0 && m0 < 512){
    ull ss2[8];
    #pragma unroll
    for (int j=0;j<8;j++){
      ull s2 = 0ull;
      #pragma unroll
      for (int i=0;i<8;i++) s2 = ffma2(acc[i][j], acc[i][j], s2);
      ss2[j] = s2;
    }
    __syncthreads();
    #pragma unroll
    for (int j=0;j<8;j++){
      int col = tx*4 + (j>>1)*64 + (j&1)*2;
      *(ull*)&NormS[ty][col] = ss2[j];
    }
    __syncthreads();
    int g4 = (ty>>2)*4;
    #pragma unroll
    for (int j=0;j<8;j++){
      int col = tx*4 + (j>>1)*64 + (j&1)*2;
      ull n2 = *(const ull*)&NormS[g4+0][col];
      n2 = fadd2(n2, *(const ull*)&NormS[g4+1][col]);
      n2 = fadd2(n2, *(const ull*)&NormS[g4+2][col]);
      n2 = fadd2(n2, *(const ull*)&NormS[g4+3][col]);
      float2 nf = unpack2(n2);
      float f0 = 1.f/fmaxf(sqrtf(nf.x), 1e-12f);
      float f1 = 1.f/fmaxf(sqrtf(nf.y), 1e-12f);
      ull fv = pack2(f0, f1);
      #pragma unroll
      for (int i=0;i<8;i++) acc[i][j] = fmul2(acc[i][j], fv);
    }
  }

  #pragma unroll
  for (int i=0;i<8;i++){
    int m = m0 + ty*8 + i;
    float bo = (MODE==1) ? bias[m] : 0.f;
    #pragma unroll
    for (int cc=0;cc<4;cc++){
      float2 p0 = unpack2(acc[i][cc*2]);
      float2 p1 = unpack2(acc[i][cc*2+1]);
      float4 o = make_float4(p0.x+bo, p0.y+bo, p1.x+bo, p1.y+bo);
      *(float4*)(C + (size_t)m*S_TOT + n0 + tx*4 + cc*64) = o;
    }
  }
}

// ---------------- 4) probes --------------------------------------------------
__global__ void k_probes(){
  int bh = blockIdx.x >> 5, c = blockIdx.x & 31;
  int t = threadIdx.x, lane = t & 31;
  const float* qp = g_qkv + (size_t)(bh*32+c)*S_TOT;
  const float* kp = g_qkv + (size_t)(256+bh*32+c)*S_TOT;
  __shared__ float sqd[16], skd[16], sqh[64], sqw[64];
  if (t<64){ sqh[t]=0.f; sqw[t]=0.f; }
  if (t<16){ sqd[t]=0.f; skd[t]=0.f; }
  __syncthreads();
  float qW = 0.f;
  float qH[8];
  #pragma unroll
  for (int i=0;i<8;i++) qH[i]=0.f;
  #pragma unroll 1
  for (int m=0;m<16;m++){
    float qD=0.f, kD=0.f;
    #pragma unroll
    for (int i2=0;i2<8;i2++){
      int s = m*4096 + i2*512 + t;
      float qv = fabsf(qp[s]);
      float kv = fabsf(kp[s]);
      qD += qv; kD += kv; qW += qv; qH[i2] += qv;
    }
    qD = warp_sum(qD); kD = warp_sum(kD);
    if (lane==0){ atomicAdd(&sqd[m], qD); atomicAdd(&skd[m], kD); }
  }
  int hb = t >> 6;
  #pragma unroll
  for (int i2=0;i2<8;i2++){
    float v = warp_sum(qH[i2]);
    if (lane==0) atomicAdd(&sqh[i2*8 + hb], v);
  }
  atomicAdd(&sqw[t & 63], qW);
  __syncthreads();
  if (t<16){ g_qpd[(bh*32+c)*16 + t] = sqd[t]; g_kpd[(bh*32+c)*16 + t] = skd[t]; }
  if (t<64){ g_qph[(bh*32+c)*64 + t] = sqh[t]; g_qpw[(bh*32+c)*64 + t] = sqw[t]; }
}

// ---------------- 6) k probe over h (+ fused top-kD) -------------------------
__global__ void k_kprobe_h(){
  int bh = blockIdx.x>>5, c = blockIdx.x&31;
  int t = threadIdx.x, lane = t&31;
  const float* kp = g_qkv + (size_t)(256+bh*32+c)*S_TOT;
  __shared__ float sh[64];
  __shared__ float scD[16];
  __shared__ int sd[4];
  if (t<64) sh[t]=0.f;
  if (t < 32){
    float qv[16], kv[16];
    const float* qb = g_qpd + (bh*32+t)*16;
    const float* kb = g_kpd + (bh*32+t)*16;
    #pragma unroll
    for (int d=0;d<16;d++){ qv[d]=qb[d]; kv[d]=kb[d]; }
    #pragma unroll
    for (int d=0;d<16;d++){
      float v = warp_sum(qv[d]*kv[d]);
      if (t==0) scD[d]=v;
    }
    if (t==0){
      unsigned used=0;
      for (int r=0;r<4;r++){
        float best=-3.4e38f; int bi=0;
        for (int d=0;d<16;d++) if(!((used>>d)&1u) && scD[d]>best){best=scD[d];bi=d;}
        used|=1u<<bi; sd[r]=bi;
      }
    }
  }
  __syncthreads();
  if (c==0 && t<4) g_idxD[bh*4+t]=sd[t];
  float acc[8];
  #pragma unroll
  for (int i=0;i<8;i++) acc[i]=0.f;
  #pragma unroll 1
  for (int di=0; di<4; di++){
    int d = sd[di];
    #pragma unroll
    for (int i2=0;i2<8;i2++){
      int s = d*4096 + i2*512 + t;
      acc[i2] += fabsf(kp[s]);
    }
  }
  int hb = t>>6;
  #pragma unroll
  for (int i2=0;i2<8;i2++){
    float v = warp_sum(acc[i2]);
    if (lane==0) atomicAdd(&sh[i2*8+hb], v);
  }
  __syncthreads();
  if (t<64) g_kph[(bh*32+c)*64+t] = sh[t];
}

// ---------------- 8) k probe over w (+ fused top-kH) -------------------------
__global__ void k_kprobe_w(){
  int bh = blockIdx.x>>5, c = blockIdx.x&31;
  int t = threadIdx.x;
  const float* kp = g_qkv + (size_t)(256+bh*32+c)*S_TOT;
  __shared__ float sw[64];
  __shared__ float scH[64];
  __shared__ int sd[4], shh[8];
  if (t<64) sw[t]=0.f;
  if (t<4)  sd[t]=g_idxD[bh*4+t];
  {
    int w = t>>5, lane = t&31;
    const float* qb = g_qph + (bh*32+lane)*64;
    const float* kb = g_kph + (bh*32+lane)*64;
    #pragma unroll
    for (int i=0;i<8;i++){
      int d = w*8+i;
      float v = warp_sum(qb[d]*kb[d]);
      if (lane==0) scH[d]=v;
    }
  }
  __syncthreads();
  if (t==0){
    ull used=0ull;
    for (int r=0;r<8;r++){
      float best=-3.4e38f; int bi=0;
      for (int d=0;d<64;d++) if(!((used>>d)&1ull) && scH[d]>best){best=scH[d];bi=d;}
      used|=1ull<<bi; shh[r]=bi;
    }
  }
  __syncthreads();
  if (c==0 && t<8) g_idxH[bh*8+t]=shh[t];
  float acc = 0.f;
  int r = t>>6, w = t&63;
  #pragma unroll
  for (int it=0; it<8; it++){
    int combo = r + it*4;
    int di = combo>>3, hi = combo&7;
    int s = sd[di]*4096 + shh[hi]*64 + w;
    acc += fabsf(kp[s]);
  }
  atomicAdd(&sw[w], acc);
  __syncthreads();
  if (t<64) g_kpw[(bh*32+c)*64+t] = sw[t];
}

// ---------------- 10) gather pruned K/V (+ fused top-kW) ---------------------
__global__ void k_gather(){
  int bh = blockIdx.y;
  int t = threadIdx.x;
  __shared__ float scW[64];
  __shared__ int sd[4], sh8[8], sw8[8];
  if (t<4) sd[t]=g_idxD[bh*4+t];
  if (t<8) sh8[t]=g_idxH[bh*8+t];
  {
    int w = t>>5, lane = t&31;
    const float* qb = g_qpw + (bh*32+lane)*64;
    const float* kb = g_kpw + (bh*32+lane)*64;
    #pragma unroll
    for (int i=0;i<8;i++){
      int d = w*8+i;
      float v = warp_sum(qb[d]*kb[d]);
      if (lane==0) scW[d]=v;
    }
  }
  __syncthreads();
  if (t==0){
    ull used=0ull;
    for (int r=0;r<8;r++){
      float best=-3.4e38f; int bi=0;
      for (int d=0;d<64;d++) if(!((used>>d)&1ull) && scW[d]>best){best=scW[d];bi=d;}
      used|=1ull<<bi; sw8[r]=bi;
    }
  }
  __syncthreads();
  int j = blockIdx.x*8 + (t>>5);
  int c = t & 31;
  int di = j>>6, hi = (j>>3)&7, wi = j&7;
  int s = sd[di]*4096 + sh8[hi]*64 + sw8[wi];
  g_kf[(bh*256+j)*32 + c] = g_qkv[(size_t)(256+bh*32+c)*S_TOT + s];
  g_vf[(bh*256+j)*32 + c] = g_qkv[(size_t)(512+bh*32+c)*S_TOT + s];
}

// ---------------- 11) attention: 256 thr, 2 queries/thread (R2-proven) -------
__global__ void __launch_bounds__(256) k_attn(){
  extern __shared__ float smem[];
  float* sk = smem;            // 256*32
  float* sv = smem + 8192;     // 256*32
  int bh = blockIdx.y, t = threadIdx.x;
  const float4* kf4 = (const float4*)(g_kf + (size_t)bh*8192);
  const float4* vf4 = (const float4*)(g_vf + (size_t)bh*8192);
  #pragma unroll
  for (int i=0;i<8;i++){
    ((float4*)sk)[t + i*256] = kf4[t + i*256];
    ((float4*)sv)[t + i*256] = vf4[t + i*256];
  }
  __syncthreads();
  const float LOG2E = 1.4426950408889634f;
  int s0 = blockIdx.x*512 + t;
  int s1 = s0 + 256;
  ull q0[16], q1[16];
  #pragma unroll
  for (int c=0;c<16;c++){
    const float* p = g_qkv + (size_t)(bh*32 + 2*c)*S_TOT;
    q0[c] = pack2(p[s0]*LOG2E, p[S_TOT + s0]*LOG2E);
    q1[c] = pack2(p[s1]*LOG2E, p[S_TOT + s1]*LOG2E);
  }
  ull o0[16], o1[16];
  #pragma unroll
  for (int c=0;c<16;c++){ o0[c]=0ull; o1[c]=0ull; }
  float l0=0.f, l1=0.f;
  #pragma unroll 2
  for (int j=0;j<256;j++){
    const ulonglong2* kp = (const ulonglong2*)(sk + j*32);
    ull sA0=0ull,sA1=0ull,sB0=0ull,sB1=0ull;
    #pragma unroll
    for (int u=0;u<8;u++){
      ulonglong2 x = kp[u];
      sA0 = ffma2(q0[2*u],   x.x, sA0);
      sA1 = ffma2(q0[2*u+1], x.y, sA1);
      sB0 = ffma2(q1[2*u],   x.x, sB0);
      sB1 = ffma2(q1[2*u+1], x.y, sB1);
    }
    float2 fa = unpack2(fadd2(sA0,sA1));
    float2 fb = unpack2(fadd2(sB0,sB1));
    float p0 = ex2f(fa.x + fa.y);
    float p1 = ex2f(fb.x + fb.y);
    l0 += p0; l1 += p1;
    ull pd0 = dup2(p0), pd1 = dup2(p1);
    const ulonglong2* vp = (const ulonglong2*)(sv + j*32);
    #pragma unroll
    for (int u=0;u<8;u++){
      ulonglong2 x = vp[u];
      o0[2*u]   = ffma2(pd0, x.x, o0[2*u]);
      o0[2*u+1] = ffma2(pd0, x.y, o0[2*u+1]);
      o1[2*u]   = ffma2(pd1, x.x, o1[2*u]);
      o1[2*u+1] = ffma2(pd1, x.y, o1[2*u+1]);
    }
  }
  ull d0 = dup2(1.f/l0), d1 = dup2(1.f/l1);
  float4* ob0 = (float4*)(g_aout + ((size_t)bh*S_TOT + (size_t)s0)*32u);
  #pragma unroll
  for (int u=0;u<8;u++){
    float2 a = unpack2(fmul2(o0[2*u], d0));
    float2 b = unpack2(fmul2(o0[2*u+1], d0));
    ob0[u] = make_float4(a.x, a.y, b.x, b.y);
  }
  float4* ob1 = (float4*)(g_aout + ((size_t)bh*S_TOT + (size_t)s1)*32u);
  #pragma unroll
  for (int u=0;u<8;u++){
    float2 a = unpack2(fmul2(o1[2*u], d1));
    float2 b = unpack2(fmul2(o1[2*u+1], d1));
    ob1[u] = make_float4(a.x, a.y, b.x, b.y);
  }
}

// ---------------- host ------------------------------------------------------
extern "C" void kernel_launch(void* const* d_in, const int* in_sizes, int n_in,
                              void* d_out, int out_size) {
  (void)in_sizes; (void)n_in; (void)out_size;
  const float* x     = (const float*)d_in[0];
  const float* g     = (const float*)d_in[1];
  const float* b     = (const float*)d_in[2];
  const float* wqkv  = (const float*)d_in[3];
  const float* wout  = (const float*)d_in[4];
  const float* bout  = (const float*)d_in[5];
  float* out = (float*)d_out;

  k_wsplit<<<384, 256>>>(wqkv);
  k_lnsplit<<<S_TOT/128, 128>>>(x, g, b);
  k_qkv_mma<<<dim3(S_TOT/64, 6), 128>>>();
  k_probes<<<256, 512>>>();
  k_kprobe_h<<<256, 512>>>();
  k_kprobe_w<<<256, 256>>>();
  k_gather<<<dim3(32, 8), 256>>>();
  cudaFuncSetAttribute((const void*)k_attn,
                       cudaFuncAttributeMaxDynamicSharedMemorySize, 65536);
  k_attn<<<dim3(S_TOT/512, 8), 256, 65536>>>();
  k_gemm<256,1><<<dim3(S_TOT/256, 1), 256>>>(wout, nullptr, out, nullptr, nullptr, bout);
}

// round 16
// speedup vs baseline: 1.5387x; 1.0766x over previous
#include <cuda_runtime.h>
#include <cuda_bf16.h>
#include <math.h>

#define S_TOT 65536
#define CDIM 128
typedef unsigned long long ull;

extern __shared__ char dynsmem[];

// ---------------- scratch ----------------------------------------------------
__device__ float g_mean[S_TOT];   // unused at runtime (template compile)
__device__ float g_rstd[S_TOT];
__device__ float g_qkv[768u * S_TOT];        // q[0:256] k[256:512] v[512:768]
__device__ float g_aout[8u * S_TOT * 32u];   // [bh][query][c]
__device__ float g_qpd[8*32*16];
__device__ float g_qph[8*32*64];
__device__ float g_qpw[8*32*64];
__device__ float g_kpd[8*32*16];
__device__ float g_kph[8*32*64];
__device__ float g_kpw[8*32*64];
__device__ int   g_idxD[8*4];
__device__ int   g_idxH[8*8];
__device__ float g_kf[8*256*32];
__device__ float g_vf[8*256*32];
// split-bf16 concatenated operands: K' = 384
// A' = [Whi | Whi | Wlo]  (768 x 384),  B' = [Xhi | Xlo | Xhi]  (65536 x 384)
__device__ __align__(16) __nv_bfloat16 g_w[768u*384u];
__device__ __align__(16) __nv_bfloat16 g_xn[(size_t)S_TOT*384u];

// ---------------- f32x2 helpers ----------------------------------------------
__device__ __forceinline__ ull ffma2(ull a, ull b, ull c){
  ull d; asm("fma.rn.f32x2 %0, %1, %2, %3;" : "=l"(d) : "l"(a), "l"(b), "l"(c)); return d;
}
__device__ __forceinline__ ull fmul2(ull a, ull b){
  ull d; asm("mul.rn.f32x2 %0, %1, %2;" : "=l"(d) : "l"(a), "l"(b)); return d;
}
__device__ __forceinline__ ull fadd2(ull a, ull b){
  ull d; asm("add.rn.f32x2 %0, %1, %2;" : "=l"(d) : "l"(a), "l"(b)); return d;
}
__device__ __forceinline__ ull dup2(float x){
  unsigned r = __float_as_uint(x);
  ull d; asm("mov.b64 %0, {%1, %2};" : "=l"(d) : "r"(r), "r"(r)); return d;
}
__device__ __forceinline__ ull pack2(float x, float y){
  ull d; asm("mov.b64 %0, {%1, %2};" : "=l"(d) : "r"(__float_as_uint(x)), "r"(__float_as_uint(y))); return d;
}
__device__ __forceinline__ float2 unpack2(ull v){
  unsigned lo, hi; asm("mov.b64 {%0, %1}, %2;" : "=r"(lo), "=r"(hi) : "l"(v));
  return make_float2(__uint_as_float(lo), __uint_as_float(hi));
}
__device__ __forceinline__ float ex2f(float x){
  float r; asm("ex2.approx.f32 %0, %1;" : "=f"(r) : "f"(x)); return r;
}
__device__ __forceinline__ float warp_sum(float v){
  #pragma unroll
  for (int o=16;o;o>>=1) v += __shfl_xor_sync(0xffffffffu, v, o);
  return v;
}

// ---------------- 0a) build A' = [Whi | Whi | Wlo] ---------------------------
__global__ void k_wsplit(const float* __restrict__ w){
  int i = blockIdx.x*256 + threadIdx.x;   // 98304 total
  int m = i >> 7, c = i & 127;
  float v = w[i];
  __nv_bfloat16 h = __float2bfloat16(v);
  __nv_bfloat16 l = __float2bfloat16(v - __bfloat162float(h));
  g_w[(size_t)m*384 + c]       = h;
  g_w[(size_t)m*384 + 128 + c] = h;
  g_w[(size_t)m*384 + 256 + c] = l;
}

// ---------------- 0b) LayerNorm + split + transpose: B' = [Xhi|Xlo|Xhi] ------
__global__ void __launch_bounds__(128) k_lnsplit(const float* __restrict__ x,
    const float* __restrict__ gg, const float* __restrict__ bb){
  __shared__ ull sh[128][33];
  int t = threadIdx.x;
  int sBase = blockIdx.x*128;
  int s = sBase + t;
  float xv[128];
  float sum=0.f, sq=0.f;
  #pragma unroll 4
  for (int c=0;c<128;c++){
    float v = x[(size_t)c*S_TOT + s];
    xv[c]=v; sum+=v; sq+=v*v;
  }
  float mn = sum*(1.f/128.f);
  float rs = 1.f/sqrtf(sq*(1.f/128.f)-mn*mn + 1e-5f);
  #pragma unroll 4
  for (int c=0;c<128;c++) xv[c] = (xv[c]-mn)*rs*gg[c] + bb[c];
  // ---- HI pass: write to cols [0,128) and duplicate at [256,384) ----
  #pragma unroll
  for (int q=0;q<32;q++){
    ull p = 0;
    #pragma unroll
    for (int e=0;e<4;e++){
      __nv_bfloat16 h = __float2bfloat16(xv[q*4+e]);
      unsigned short u = *(unsigned short*)&h;
      p |= (ull)u << (e*16);
    }
    sh[t][q] = p;
  }
  __syncthreads();
  #pragma unroll
  for (int it=0; it<16; it++){
    int chunk = it*128 + t;
    int row = chunk>>4, seg = chunk&15;
    ulonglong2 v = make_ulonglong2(sh[row][seg*2], sh[row][seg*2+1]);
    __nv_bfloat16* base = g_xn + ((size_t)(sBase+row))*384 + seg*8;
    *(ulonglong2*)base = v;
    *(ulonglong2*)(base + 256) = v;
  }
  __syncthreads();
  // ---- LO pass: write to cols [128,256) ----
  #pragma unroll
  for (int q=0;q<32;q++){
    ull p = 0;
    #pragma unroll
    for (int e=0;e<4;e++){
      float v = xv[q*4+e];
      __nv_bfloat16 h = __float2bfloat16(v);
      __nv_bfloat16 l = __float2bfloat16(v - __bfloat162float(h));
      unsigned short u = *(unsigned short*)&l;
      p |= (ull)u << (e*16);
    }
    sh[t][q] = p;
  }
  __syncthreads();
  #pragma unroll
  for (int it=0; it<16; it++){
    int chunk = it*128 + t;
    int row = chunk>>4, seg = chunk&15;
    ulonglong2 v = make_ulonglong2(sh[row][seg*2], sh[row][seg*2+1]);
    *(ulonglong2*)(g_xn + ((size_t)(sBase+row))*384 + 128 + seg*8) = v;
  }
}

// ---------------- 2) QKV GEMM: B-resident HMMA, 256 thr, tile 128n x all-m ---
__device__ __forceinline__ void mma16816(float* c, const unsigned* a, const unsigned* b){
  asm volatile(
    "mma.sync.aligned.m16n8k16.row.col.f32.bf16.bf16.f32 "
    "{%0,%1,%2,%3}, {%4,%5,%6,%7}, {%8,%9}, {%0,%1,%2,%3};"
    : "+f"(c[0]), "+f"(c[1]), "+f"(c[2]), "+f"(c[3])
    : "r"(a[0]), "r"(a[1]), "r"(a[2]), "r"(a[3]), "r"(b[0]), "r"(b[1]));
}

#define APITCH 40
#define BPITCH 392
#define QKV_SMEM (128*BPITCH*2 + 2*128*APITCH*2)   // 100352 + 20480 = 120832

__global__ void __launch_bounds__(256) k_qkv_mma(){
  __nv_bfloat16* Bs = (__nv_bfloat16*)dynsmem;                     // 128 x BPITCH
  __nv_bfloat16* As = (__nv_bfloat16*)(dynsmem + 128*BPITCH*2);    // 2 x 128 x APITCH
  int t = threadIdx.x;
  int wid = t>>5, lane = t&31;
  int g = lane>>2, tig = lane&3;
  int wm = wid>>2, wn = wid&3;      // 2 x 4 warp grid; warp tile 64m x 32n
  int n0 = blockIdx.x*128;
  int r = t>>1, h = (t&1)*16;

  // ---- load B tile (128 rows x 384 halves) once ----
  #pragma unroll
  for (int seg=0; seg<12; seg++){
    int off = h + seg*32;
    const __nv_bfloat16* src = g_xn + (size_t)(n0+r)*384 + off;
    ulonglong2 v0 = *(const ulonglong2*)src;
    ulonglong2 v1 = *(const ulonglong2*)(src + 8);
    *(ulonglong2*)&Bs[r*BPITCH + off]     = v0;
    *(ulonglong2*)&Bs[r*BPITCH + off + 8] = v1;
  }
  // ---- prologue: stage A chunk (mblk 0, k0 0) into As[0] ----
  {
    const __nv_bfloat16* src = g_w + (size_t)r*384 + h;
    ulonglong2 v0 = *(const ulonglong2*)src;
    ulonglong2 v1 = *(const ulonglong2*)(src + 8);
    *(ulonglong2*)&As[r*APITCH + h]     = v0;
    *(ulonglong2*)&As[r*APITCH + h + 8] = v1;
  }
  __syncthreads();
  int st = 0;

  for (int mblk=0; mblk<6; mblk++){
    float c[4][4][4];
    #pragma unroll
    for (int mt=0;mt<4;mt++)
      #pragma unroll
      for (int nt=0;nt<4;nt++)
        #pragma unroll
        for (int e=0;e<4;e++) c[mt][nt][e]=0.f;

    for (int kc=0; kc<12; kc++){
      // prefetch next chunk (mblk,kc+1) / (mblk+1,0) into registers
      int nm = mblk, nk = kc+1;
      if (nk==12){ nm = mblk+1; nk = 0; }
      bool more = (nm < 6);
      ulonglong2 p0, p1;
      if (more){
        const __nv_bfloat16* src = g_w + (size_t)(nm*128 + r)*384 + nk*32 + h;
        p0 = *(const ulonglong2*)src;
        p1 = *(const ulonglong2*)(src + 8);
      }
      const __nv_bfloat16* Ac = As + st*128*APITCH;
      #pragma unroll
      for (int ks=0;ks<2;ks++){
        int kk = ks*16;
        unsigned a[4][4], b[4][2];
        #pragma unroll
        for (int mt=0;mt<4;mt++){
          int mr = (wm*64 + mt*16 + g)*APITCH + kk + tig*2;
          a[mt][0] = *(const unsigned*)&Ac[mr];
          a[mt][1] = *(const unsigned*)&Ac[mr + 8*APITCH];
          a[mt][2] = *(const unsigned*)&Ac[mr + 8];
          a[mt][3] = *(const unsigned*)&Ac[mr + 8*APITCH + 8];
        }
        // FIX (R15 bug): B fragment must index the CURRENT k-chunk within
        // the full-width resident tile: + kc*32.
        #pragma unroll
        for (int nt=0;nt<4;nt++){
          int nr = (wn*32 + nt*8 + g)*BPITCH + kc*32 + kk + tig*2;
          b[nt][0] = *(const unsigned*)&Bs[nr];
          b[nt][1] = *(const unsigned*)&Bs[nr + 8];
        }
        #pragma unroll
        for (int mt=0;mt<4;mt++)
          #pragma unroll
          for (int nt=0;nt<4;nt++)
            mma16816(c[mt][nt], a[mt], b[nt]);
      }
      if (more){
        __nv_bfloat16* dst = As + (st^1)*128*APITCH + r*APITCH + h;
        *(ulonglong2*)dst       = p0;
        *(ulonglong2*)(dst + 8) = p1;
      }
      __syncthreads();
      st ^= 1;
    }

    // ---- epilogue for this m-block ----
    if (mblk < 4){   // q,k rows: per-head l2-norm (head = 32 rows = 2 m-tiles)
      #pragma unroll
      for (int hh=0; hh<2; hh++){
        #pragma unroll
        for (int nt=0; nt<4; nt++){
          float* f0 = c[hh*2][nt];
          float* f1 = c[hh*2+1][nt];
          float sA = f0[0]*f0[0] + f0[2]*f0[2] + f1[0]*f1[0] + f1[2]*f1[2];
          float sB = f0[1]*f0[1] + f0[3]*f0[3] + f1[1]*f1[1] + f1[3]*f1[3];
          #pragma unroll
          for (int o=4;o<=16;o<<=1){
            sA += __shfl_xor_sync(0xffffffffu, sA, o);
            sB += __shfl_xor_sync(0xffffffffu, sB, o);
          }
          float fA = 1.f/fmaxf(sqrtf(sA), 1e-12f);
          float fB = 1.f/fmaxf(sqrtf(sB), 1e-12f);
          f0[0]*=fA; f0[2]*=fA; f1[0]*=fA; f1[2]*=fA;
          f0[1]*=fB; f0[3]*=fB; f1[1]*=fB; f1[3]*=fB;
        }
      }
    }
    #pragma unroll
    for (int mt=0;mt<4;mt++){
      int m = mblk*128 + wm*64 + mt*16;
      #pragma unroll
      for (int nt=0;nt<4;nt++){
        int s = n0 + wn*32 + nt*8 + tig*2;
        *(float2*)(g_qkv + (size_t)(m+g)*S_TOT + s)   = make_float2(c[mt][nt][0], c[mt][nt][1]);
        *(float2*)(g_qkv + (size_t)(m+g+8)*S_TOT + s) = make_float2(c[mt][nt][2], c[mt][nt][3]);
      }
    }
  }
}

// ---------------- 12) SGEMM (proj only; R2-proven config) --------------------
template<int KDIM, int MODE>
__global__ void __launch_bounds__(256) k_gemm(
    const float* __restrict__ A, const float* __restrict__ Bx,
    float* __restrict__ Cx, const float* __restrict__ gg,
    const float* __restrict__ bb, const float* __restrict__ bias)
{
  const float* B = (MODE==0) ? Bx : g_aout;
  float* C = (MODE==0) ? g_qkv : Cx;
  __shared__ __align__(16) float As[2][8][128];
  __shared__ __align__(16) float Bs[2][8][256];
  __shared__ __align__(16) float NormS[16][256];
  int t = threadIdx.x;
  int m0 = blockIdx.y*128, n0 = blockIdx.x*256;
  int tx = t & 15, ty = t >> 4;

  int lar = t >> 1, lak = (t & 1) * 4;
  int lbk = t >> 5, lbc = (t & 31) * 4;

  float4 mean4[2], rstd4[2];
  if (MODE==0){
    #pragma unroll
    for (int h=0;h<2;h++){
      mean4[h] = *(const float4*)&g_mean[n0 + lbc + h*128];
      rstd4[h] = *(const float4*)&g_rstd[n0 + lbc + h*128];
    }
  }

  ull acc[8][8];
  #pragma unroll
  for (int i=0;i<8;i++)
    #pragma unroll
    for (int j=0;j<8;j++) acc[i][j] = 0ull;

  const int NS = KDIM/8;
  {
    float4 a4 = *(const float4*)(A + (size_t)(m0+lar)*KDIM + lak);
    As[0][lak+0][lar]=a4.x; As[0][lak+1][lar]=a4.y;
    As[0][lak+2][lar]=a4.z; As[0][lak+3][lar]=a4.w;
    float gk=1.f, bk=0.f;
    if (MODE==0){ gk = gg[lbk]; bk = bb[lbk]; }
    #pragma unroll
    for (int h=0;h<2;h++){
      float4 b4 = *(const float4*)(B + (size_t)lbk*S_TOT + n0 + lbc + h*128);
      if (MODE==0){
        b4.x = (b4.x-mean4[h].x)*rstd4[h].x*gk + bk;
        b4.y = (b4.y-mean4[h].y)*rstd4[h].y*gk + bk;
        b4.z = (b4.z-mean4[h].z)*rstd4[h].z*gk + bk;
        b4.w = (b4.w-mean4[h].w)*rstd4[h].w*gk + bk;
      }
      *(float4*)&Bs[0][lbk][lbc + h*128] = b4;
    }
  }
  __syncthreads();
  int st = 0;
  for (int ks=0; ks<NS; ks++){
    float4 a4n; float4 b4n[2];
    bool more = (ks+1 < NS);
    if (more){
      int k0 = (ks+1)*8;
      a4n = *(const float4*)(A + (size_t)(m0+lar)*KDIM + k0 + lak);
      float gk=1.f, bk=0.f;
      if (MODE==0){ gk = gg[k0+lbk]; bk = bb[k0+lbk]; }
      #pragma unroll
      for (int h=0;h<2;h++){
        float4 b4 = *(const float4*)(B + (size_t)(k0+lbk)*S_TOT + n0 + lbc + h*128);
        if (MODE==0){
          b4.x = (b4.x-mean4[h].x)*rstd4[h].x*gk + bk;
          b4.y = (b4.y-mean4[h].y)*rstd4[h].y*gk + bk;
          b4.z = (b4.z-mean4[h].z)*rstd4[h].z*gk + bk;
          b4.w = (b4.w-mean4[h].w)*rstd4[h].w*gk + bk;
        }
        b4n[h] = b4;
      }
    }
    #pragma unroll
    for (int kk=0;kk<8;kk++){
      float4 av0 = *(const float4*)&As[st][kk][ty*8];
      float4 av1 = *(const float4*)&As[st][kk][ty*8+4];
      float a[8] = {av0.x,av0.y,av0.z,av0.w,av1.x,av1.y,av1.z,av1.w};
      ull b2[8];
      #pragma unroll
      for (int cc=0;cc<4;cc++){
        ulonglong2 bp = *(const ulonglong2*)&Bs[st][kk][tx*4 + cc*64];
        b2[cc*2] = bp.x; b2[cc*2+1] = bp.y;
      }
      #pragma unroll
      for (int i=0;i<8;i++){
        ull da = dup2(a[i]);
        #pragma unroll
        for (int j=0;j<8;j++) acc[i][j] = ffma2(da, b2[j], acc[i][j]);
      }
    }
    if (more){
      int ns = st^1;
      As[ns][lak+0][lar]=a4n.x; As[ns][lak+1][lar]=a4n.y;
      As[ns][lak+2][lar]=a4n.z; As[ns][lak+3][lar]=a4n.w;
      *(float4*)&Bs[ns][lbk][lbc]       = b4n[0];
      *(float4*)&Bs[ns][lbk][lbc + 128] = b4n[1];
      __syncthreads();
      st = ns;
    }
  }

  if (MODE==0 && m0 < 512){
    ull ss2[8];
    #pragma unroll
    for (int j=0;j<8;j++){
      ull s2 = 0ull;
      #pragma unroll
      for (int i=0;i<8;i++) s2 = ffma2(acc[i][j], acc[i][j], s2);
      ss2[j] = s2;
    }
    __syncthreads();
    #pragma unroll
    for (int j=0;j<8;j++){
      int col = tx*4 + (j>>1)*64 + (j&1)*2;
      *(ull*)&NormS[ty][col] = ss2[j];
    }
    __syncthreads();
    int g4 = (ty>>2)*4;
    #pragma unroll
    for (int j=0;j<8;j++){
      int col = tx*4 + (j>>1)*64 + (j&1)*2;
      ull n2 = *(const ull*)&NormS[g4+0][col];
      n2 = fadd2(n2, *(const ull*)&NormS[g4+1][col]);
      n2 = fadd2(n2, *(const ull*)&NormS[g4+2][col]);
      n2 = fadd2(n2, *(const ull*)&NormS[g4+3][col]);
      float2 nf = unpack2(n2);
      float f0 = 1.f/fmaxf(sqrtf(nf.x), 1e-12f);
      float f1 = 1.f/fmaxf(sqrtf(nf.y), 1e-12f);
      ull fv = pack2(f0, f1);
      #pragma unroll
      for (int i=0;i<8;i++) acc[i][j] = fmul2(acc[i][j], fv);
    }
  }

  #pragma unroll
  for (int i=0;i<8;i++){
    int m = m0 + ty*8 + i;
    float bo = (MODE==1) ? bias[m] : 0.f;
    #pragma unroll
    for (int cc=0;cc<4;cc++){
      float2 p0 = unpack2(acc[i][cc*2]);
      float2 p1 = unpack2(acc[i][cc*2+1]);
      float4 o = make_float4(p0.x+bo, p0.y+bo, p1.x+bo, p1.y+bo);
      *(float4*)(C + (size_t)m*S_TOT + n0 + tx*4 + cc*64) = o;
    }
  }
}

// ---------------- 4) probes --------------------------------------------------
__global__ void k_probes(){
  int bh = blockIdx.x >> 5, c = blockIdx.x & 31;
  int t = threadIdx.x, lane = t & 31;
  const float* qp = g_qkv + (size_t)(bh*32+c)*S_TOT;
  const float* kp = g_qkv + (size_t)(256+bh*32+c)*S_TOT;
  __shared__ float sqd[16], skd[16], sqh[64], sqw[64];
  if (t<64){ sqh[t]=0.f; sqw[t]=0.f; }
  if (t<16){ sqd[t]=0.f; skd[t]=0.f; }
  __syncthreads();
  float qW = 0.f;
  float qH[8];
  #pragma unroll
  for (int i=0;i<8;i++) qH[i]=0.f;
  #pragma unroll 1
  for (int m=0;m<16;m++){
    float qD=0.f, kD=0.f;
    #pragma unroll
    for (int i2=0;i2<8;i2++){
      int s = m*4096 + i2*512 + t;
      float qv = fabsf(qp[s]);
      float kv = fabsf(kp[s]);
      qD += qv; kD += kv; qW += qv; qH[i2] += qv;
    }
    qD = warp_sum(qD); kD = warp_sum(kD);
    if (lane==0){ atomicAdd(&sqd[m], qD); atomicAdd(&skd[m], kD); }
  }
  int hb = t >> 6;
  #pragma unroll
  for (int i2=0;i2<8;i2++){
    float v = warp_sum(qH[i2]);
    if (lane==0) atomicAdd(&sqh[i2*8 + hb], v);
  }
  atomicAdd(&sqw[t & 63], qW);
  __syncthreads();
  if (t<16){ g_qpd[(bh*32+c)*16 + t] = sqd[t]; g_kpd[(bh*32+c)*16 + t] = skd[t]; }
  if (t<64){ g_qph[(bh*32+c)*64 + t] = sqh[t]; g_qpw[(bh*32+c)*64 + t] = sqw[t]; }
}

// ---------------- 6) k probe over h (+ fused top-kD) -------------------------
__global__ void k_kprobe_h(){
  int bh = blockIdx.x>>5, c = blockIdx.x&31;
  int t = threadIdx.x, lane = t&31;
  const float* kp = g_qkv + (size_t)(256+bh*32+c)*S_TOT;
  __shared__ float sh[64];
  __shared__ float scD[16];
  __shared__ int sd[4];
  if (t<64) sh[t]=0.f;
  if (t < 32){
    float qv[16], kv[16];
    const float* qb = g_qpd + (bh*32+t)*16;
    const float* kb = g_kpd + (bh*32+t)*16;
    #pragma unroll
    for (int d=0;d<16;d++){ qv[d]=qb[d]; kv[d]=kb[d]; }
    #pragma unroll
    for (int d=0;d<16;d++){
      float v = warp_sum(qv[d]*kv[d]);
      if (t==0) scD[d]=v;
    }
    if (t==0){
      unsigned used=0;
      for (int r=0;r<4;r++){
        float best=-3.4e38f; int bi=0;
        for (int d=0;d<16;d++) if(!((used>>d)&1u) && scD[d]>best){best=scD[d];bi=d;}
        used|=1u<<bi; sd[r]=bi;
      }
    }
  }
  __syncthreads();
  if (c==0 && t<4) g_idxD[bh*4+t]=sd[t];
  float acc[8];
  #pragma unroll
  for (int i=0;i<8;i++) acc[i]=0.f;
  #pragma unroll 1
  for (int di=0; di<4; di++){
    int d = sd[di];
    #pragma unroll
    for (int i2=0;i2<8;i2++){
      int s = d*4096 + i2*512 + t;
      acc[i2] += fabsf(kp[s]);
    }
  }
  int hb = t>>6;
  #pragma unroll
  for (int i2=0;i2<8;i2++){
    float v = warp_sum(acc[i2]);
    if (lane==0) atomicAdd(&sh[i2*8+hb], v);
  }
  __syncthreads();
  if (t<64) g_kph[(bh*32+c)*64+t] = sh[t];
}

// ---------------- 8) k probe over w (+ fused top-kH) -------------------------
__global__ void k_kprobe_w(){
  int bh = blockIdx.x>>5, c = blockIdx.x&31;
  int t = threadIdx.x;
  const float* kp = g_qkv + (size_t)(256+bh*32+c)*S_TOT;
  __shared__ float sw[64];
  __shared__ float scH[64];
  __shared__ int sd[4], shh[8];
  if (t<64) sw[t]=0.f;
  if (t<4)  sd[t]=g_idxD[bh*4+t];
  {
    int w = t>>5, lane = t&31;
    const float* qb = g_qph + (bh*32+lane)*64;
    const float* kb = g_kph + (bh*32+lane)*64;
    #pragma unroll
    for (int i=0;i<8;i++){
      int d = w*8+i;
      float v = warp_sum(qb[d]*kb[d]);
      if (lane==0) scH[d]=v;
    }
  }
  __syncthreads();
  if (t==0){
    ull used=0ull;
    for (int r=0;r<8;r++){
      float best=-3.4e38f; int bi=0;
      for (int d=0;d<64;d++) if(!((used>>d)&1ull) && scH[d]>best){best=scH[d];bi=d;}
      used|=1ull<<bi; shh[r]=bi;
    }
  }
  __syncthreads();
  if (c==0 && t<8) g_idxH[bh*8+t]=shh[t];
  float acc = 0.f;
  int r = t>>6, w = t&63;
  #pragma unroll
  for (int it=0; it<8; it++){
    int combo = r + it*4;
    int di = combo>>3, hi = combo&7;
    int s = sd[di]*4096 + shh[hi]*64 + w;
    acc += fabsf(kp[s]);
  }
  atomicAdd(&sw[w], acc);
  __syncthreads();
  if (t<64) g_kpw[(bh*32+c)*64+t] = sw[t];
}

// ---------------- 10) gather pruned K/V (+ fused top-kW) ---------------------
__global__ void k_gather(){
  int bh = blockIdx.y;
  int t = threadIdx.x;
  __shared__ float scW[64];
  __shared__ int sd[4], sh8[8], sw8[8];
  if (t<4) sd[t]=g_idxD[bh*4+t];
  if (t<8) sh8[t]=g_idxH[bh*8+t];
  {
    int w = t>>5, lane = t&31;
    const float* qb = g_qpw + (bh*32+lane)*64;
    const float* kb = g_kpw + (bh*32+lane)*64;
    #pragma unroll
    for (int i=0;i<8;i++){
      int d = w*8+i;
      float v = warp_sum(qb[d]*kb[d]);
      if (lane==0) scW[d]=v;
    }
  }
  __syncthreads();
  if (t==0){
    ull used=0ull;
    for (int r=0;r<8;r++){
      float best=-3.4e38f; int bi=0;
      for (int d=0;d<64;d++) if(!((used>>d)&1ull) && scW[d]>best){best=scW[d];bi=d;}
      used|=1ull<<bi; sw8[r]=bi;
    }
  }
  __syncthreads();
  int j = blockIdx.x*8 + (t>>5);
  int c = t & 31;
  int di = j>>6, hi = (j>>3)&7, wi = j&7;
  int s = sd[di]*4096 + sh8[hi]*64 + sw8[wi];
  g_kf[(bh*256+j)*32 + c] = g_qkv[(size_t)(256+bh*32+c)*S_TOT + s];
  g_vf[(bh*256+j)*32 + c] = g_qkv[(size_t)(512+bh*32+c)*S_TOT + s];
}

// ---------------- 11) attention: 256 thr, 2 queries/thread (R2-proven) -------
__global__ void __launch_bounds__(256) k_attn(){
  float* smem = (float*)dynsmem;
  float* sk = smem;            // 256*32
  float* sv = smem + 8192;     // 256*32
  int bh = blockIdx.y, t = threadIdx.x;
  const float4* kf4 = (const float4*)(g_kf + (size_t)bh*8192);
  const float4* vf4 = (const float4*)(g_vf + (size_t)bh*8192);
  #pragma unroll
  for (int i=0;i<8;i++){
    ((float4*)sk)[t + i*256] = kf4[t + i*256];
    ((float4*)sv)[t + i*256] = vf4[t + i*256];
  }
  __syncthreads();
  const float LOG2E = 1.4426950408889634f;
  int s0 = blockIdx.x*512 + t;
  int s1 = s0 + 256;
  ull q0[16], q1[16];
  #pragma unroll
  for (int c=0;c<16;c++){
    const float* p = g_qkv + (size_t)(bh*32 + 2*c)*S_TOT;
    q0[c] = pack2(p[s0]*LOG2E, p[S_TOT + s0]*LOG2E);
    q1[c] = pack2(p[s1]*LOG2E, p[S_TOT + s1]*LOG2E);
  }
  ull o0[16], o1[16];
  #pragma unroll
  for (int c=0;c<16;c++){ o0[c]=0ull; o1[c]=0ull; }
  float l0=0.f, l1=0.f;
  #pragma unroll 2
  for (int j=0;j<256;j++){
    const ulonglong2* kp = (const ulonglong2*)(sk + j*32);
    ull sA0=0ull,sA1=0ull,sB0=0ull,sB1=0ull;
    #pragma unroll
    for (int u=0;u<8;u++){
      ulonglong2 x = kp[u];
      sA0 = ffma2(q0[2*u],   x.x, sA0);
      sA1 = ffma2(q0[2*u+1], x.y, sA1);
      sB0 = ffma2(q1[2*u],   x.x, sB0);
      sB1 = ffma2(q1[2*u+1], x.y, sB1);
    }
    float2 fa = unpack2(fadd2(sA0,sA1));
    float2 fb = unpack2(fadd2(sB0,sB1));
    float p0 = ex2f(fa.x + fa.y);
    float p1 = ex2f(fb.x + fb.y);
    l0 += p0; l1 += p1;
    ull pd0 = dup2(p0), pd1 = dup2(p1);
    const ulonglong2* vp = (const ulonglong2*)(sv + j*32);
    #pragma unroll
    for (int u=0;u<8;u++){
      ulonglong2 x = vp[u];
      o0[2*u]   = ffma2(pd0, x.x, o0[2*u]);
      o0[2*u+1] = ffma2(pd0, x.y, o0[2*u+1]);
      o1[2*u]   = ffma2(pd1, x.x, o1[2*u]);
      o1[2*u+1] = ffma2(pd1, x.y, o1[2*u+1]);
    }
  }
  ull d0 = dup2(1.f/l0), d1 = dup2(1.f/l1);
  float4* ob0 = (float4*)(g_aout + ((size_t)bh*S_TOT + (size_t)s0)*32u);
  #pragma unroll
  for (int u=0;u<8;u++){
    float2 a = unpack2(fmul2(o0[2*u], d0));
    float2 b = unpack2(fmul2(o0[2*u+1], d0));
    ob0[u] = make_float4(a.x, a.y, b.x, b.y);
  }
  float4* ob1 = (float4*)(g_aout + ((size_t)bh*S_TOT + (size_t)s1)*32u);
  #pragma unroll
  for (int u=0;u<8;u++){
    float2 a = unpack2(fmul2(o1[2*u], d1));
    float2 b = unpack2(fmul2(o1[2*u+1], d1));
    ob1[u] = make_float4(a.x, a.y, b.x, b.y);
  }
}

// ---------------- host ------------------------------------------------------
extern "C" void kernel_launch(void* const* d_in, const int* in_sizes, int n_in,
                              void* d_out, int out_size) {
  (void)in_sizes; (void)n_in; (void)out_size;
  const float* x     = (const float*)d_in[0];
  const float* g     = (const float*)d_in[1];
  const float* b     = (const float*)d_in[2];
  const float* wqkv  = (const float*)d_in[3];
  const float* wout  = (const float*)d_in[4];
  const float* bout  = (const float*)d_in[5];
  float* out = (float*)d_out;

  k_wsplit<<<384, 256>>>(wqkv);
  k_lnsplit<<<S_TOT/128, 128>>>(x, g, b);
  cudaFuncSetAttribute((const void*)k_qkv_mma,
                       cudaFuncAttributeMaxDynamicSharedMemorySize, QKV_SMEM);
  k_qkv_mma<<<S_TOT/128, 256, QKV_SMEM>>>();
  k_probes<<<256, 512>>>();
  k_kprobe_h<<<256, 512>>>();
  k_kprobe_w<<<256, 256>>>();
  k_gather<<<dim3(32, 8), 256>>>();
  cudaFuncSetAttribute((const void*)k_attn,
                       cudaFuncAttributeMaxDynamicSharedMemorySize, 65536);
  k_attn<<<dim3(S_TOT/512, 8), 256, 65536>>>();
  k_gemm<256,1><<<dim3(S_TOT/256, 1), 256>>>(wout, nullptr, out, nullptr, nullptr, bout);
}